// round 14
// baseline (speedup 1.0000x reference)
#include <cuda_runtime.h>
#include <cuda_bf16.h>
#include <cstdint>

// Shapes: X[131072,256], W1[256,384], b1[384], W2[384,64], b2[64],
//         phi[5,64] i32, pi[5,64,16], out[131072,16]
#define NF  256
#define NH  384
#define NL  64
#define NO  16
#define NE  5

// ---------------------------------------------------------------------------
// Pre-split global tables (bf16 hi/lo), written by prep kernels each launch.
//   gXhi/gXlo : elementwise split of X, plain layout
//   gW1 : [s][nc(3)][k8(8)][k=32 rows][n=128]  (k-major, ldmatrix.trans at use)
//   gW2 : [s][nc(3)][n=64][k=128]              (n-major, non-trans)
// ---------------------------------------------------------------------------
__device__ __align__(16) __nv_bfloat16 gXhi[131072UL * 256UL];
__device__ __align__(16) __nv_bfloat16 gXlo[131072UL * 256UL];
__device__ __align__(16) __nv_bfloat16 gW1[2][98304];
__device__ __align__(16) __nv_bfloat16 gW2[2][24576];

__global__ void prep_x(const float* __restrict__ X) {
    size_t idx = (size_t)blockIdx.x * 256 + threadIdx.x;
    float4 v = *(const float4*)(X + idx * 4);
    __nv_bfloat162 h01 = __float22bfloat162_rn(make_float2(v.x, v.y));
    __nv_bfloat162 h23 = __float22bfloat162_rn(make_float2(v.z, v.w));
    __nv_bfloat162 l01 = __float22bfloat162_rn(make_float2(
        v.x - __bfloat162float(h01.x), v.y - __bfloat162float(h01.y)));
    __nv_bfloat162 l23 = __float22bfloat162_rn(make_float2(
        v.z - __bfloat162float(h23.x), v.w - __bfloat162float(h23.y)));
    uint2 hp, lp;
    hp.x = *(uint32_t*)&h01; hp.y = *(uint32_t*)&h23;
    lp.x = *(uint32_t*)&l01; lp.y = *(uint32_t*)&l23;
    *(uint2*)(gXhi + idx * 4) = hp;
    *(uint2*)(gXlo + idx * 4) = lp;
}

__global__ void prep_w(const float* __restrict__ W1, const float* __restrict__ W2) {
    int idx = blockIdx.x * 256 + threadIdx.x;
    if (idx < 98304) {
        // dst: [nc][k8][krow 32][n 128]
        int n  = idx & 127;
        int k  = (idx >> 7) & 31;
        int k8 = (idx >> 12) & 7;
        int nc = idx >> 15;
        float v = W1[(size_t)(k8 * 32 + k) * NH + nc * 128 + n];
        __nv_bfloat16 hi = __float2bfloat16(v);
        __nv_bfloat16 lo = __float2bfloat16(v - __bfloat162float(hi));
        gW1[0][idx] = hi;
        gW1[1][idx] = lo;
    }
    if (idx < 24576) {
        int k  = idx & 127;
        int n  = (idx >> 7) & 63;
        int nc = idx >> 13;
        float v = W2[(size_t)(nc * 128 + k) * NL + n];
        __nv_bfloat16 hi = __float2bfloat16(v);
        __nv_bfloat16 lo = __float2bfloat16(v - __bfloat162float(hi));
        gW2[0][idx] = hi;
        gW2[1][idx] = lo;
    }
}

// ---------------------------------------------------------------------------
// PTX helpers
// ---------------------------------------------------------------------------
__device__ __forceinline__ uint32_t smem_u32(const void* p) {
    uint32_t a;
    asm("{ .reg .u64 t; cvta.to.shared.u64 t, %1; cvt.u32.u64 %0, t; }"
        : "=r"(a) : "l"(p));
    return a;
}

#define CP16(dst, src) \
    asm volatile("cp.async.cg.shared.global [%0], [%1], 16;" :: "r"(dst), "l"(src))
#define CP_COMMIT() asm volatile("cp.async.commit_group;" ::: "memory")
#define CP_WAIT1()  asm volatile("cp.async.wait_group 1;" ::: "memory")
#define CP_WAIT0()  asm volatile("cp.async.wait_group 0;" ::: "memory")

#define LDM_X4(r, addr) \
    asm volatile("ldmatrix.sync.aligned.m8n8.x4.shared.b16 {%0,%1,%2,%3}, [%4];" \
        : "=r"((r)[0]), "=r"((r)[1]), "=r"((r)[2]), "=r"((r)[3]) : "r"(addr))
#define LDM_X4_T(r, addr) \
    asm volatile("ldmatrix.sync.aligned.m8n8.x4.trans.shared.b16 {%0,%1,%2,%3}, [%4];" \
        : "=r"((r)[0]), "=r"((r)[1]), "=r"((r)[2]), "=r"((r)[3]) : "r"(addr))

__device__ __forceinline__ void mma_bf16(float* c, const uint32_t* a, const uint32_t* b) {
    asm volatile("mma.sync.aligned.m16n8k16.row.col.f32.bf16.bf16.f32 "
        "{%0,%1,%2,%3}, {%4,%5,%6,%7}, {%8,%9}, {%0,%1,%2,%3};"
        : "+f"(c[0]), "+f"(c[1]), "+f"(c[2]), "+f"(c[3])
        : "r"(a[0]), "r"(a[1]), "r"(a[2]), "r"(a[3]), "r"(b[0]), "r"(b[1]));
}

__device__ __forceinline__ float fsigmoid(float v) {
    return 1.0f / (1.0f + __expf(-v));
}

// ---------------------------------------------------------------------------
// SMEM layout (bytes), 111872 total -> 2 CTAs/SM:
//   stage (37888): [XH 10240][XL 10240][W1H 8704][W1L 8704]
//     X tile [128 m][32 k] rows 80 B; W1 tile [32 k][128 n] rows 272 B
//   SM_STG0 = 0, SM_STG1 = 37888    (stages end 75776)
//   after GEMM1: Hs hi @0 (34816), Hs lo @34816  (KS=136, 272 B rows)
//   after GEMM2: lat [128][65] f32 @0
//   SM_W2  = 75776 : W2 hi 17408, lo 17408 (64 n x 272 B)
//   SM_PHI = 110592 (1280)
// ---------------------------------------------------------------------------
#define SM_STG0 0
#define SM_STG1 37888
#define SM_W2   75776
#define SM_PHI  110592
#define SMEM_TOTAL 111872

#define XLO_OFF 10240
#define W1_OFF  20480
#define W1LO    8704

__device__ __forceinline__ void issue_g1(uint32_t sbuf, int nc, int k8,
                                         size_t rowBase, int tid) {
    // X tile: 128 rows x 4 16B-chunks per split
#pragma unroll
    for (int i = 0; i < 2; i++) {
        int j = tid + i * 256;
        int row = j >> 2, c = j & 3;
        uint32_t d = sbuf + row * 80 + c * 16;
        CP16(d,           gXhi + (rowBase + row) * NF + k8 * 32 + c * 8);
        CP16(d + XLO_OFF, gXlo + (rowBase + row) * NF + k8 * 32 + c * 8);
    }
    // W1 tile: 32 k-rows x 16 chunks per split (k-major, coalesced)
    const int wbase = (nc * 8 + k8) * 32 * 128;
#pragma unroll
    for (int i = 0; i < 2; i++) {
        int j = tid + i * 256;
        int kr = j >> 4, c = j & 15;
        uint32_t d = sbuf + W1_OFF + kr * 272 + c * 16;
        CP16(d,         gW1[0] + wbase + kr * 128 + c * 8);
        CP16(d + W1LO,  gW1[1] + wbase + kr * 128 + c * 8);
    }
    CP_COMMIT();
}

__device__ __forceinline__ void issue_w2(uint32_t sb, int nc, int tid) {
#pragma unroll
    for (int i = 0; i < 4; i++) {
        int j = tid + i * 256;
        int n = j >> 4, c = j & 15;
        uint32_t d = sb + SM_W2 + n * 272 + c * 16;
        CP16(d,         gW2[0] + (nc * 64 + n) * 128 + c * 8);
        CP16(d + 17408, gW2[1] + (nc * 64 + n) * 128 + c * 8);
    }
    CP_COMMIT();
}

__global__ __launch_bounds__(256, 2)
void fused_all(const float* __restrict__ b1, const float* __restrict__ b2,
               const int* __restrict__ phi, const float* __restrict__ pi,
               float* __restrict__ out) {
    extern __shared__ char smem[];
    const uint32_t sb = smem_u32(smem);
    const int tid = threadIdx.x;
    const int wid = tid >> 5;
    const int lane = tid & 31;
    const int g = lane >> 2;
    const int tg = lane & 3;
    const size_t rowBase = (size_t)blockIdx.x * 128;

    const int a_dr = lane & 15;                    // A row sel (also B-trans k-row)
    const int a_dc = (lane >> 4) * 8;              // A col half (also B-trans n half)
    const int b_dn = (lane & 7) + (lane >> 4) * 8; // non-trans B n sel (GEMM2)
    const int b_dk = ((lane >> 3) & 1) * 8;

    // GEMM1: 4x2 warp grid, 32 rows x 64 cols per warp
    const int wm = (wid & 3) * 32;
    const int wn = (wid >> 2) * 64;
    // GEMM2: 8x1 grid, 16 rows x 64 cols per warp
    const int wm2 = wid * 16;

    {   // phi -> smem
        int* phis = (int*)(smem + SM_PHI);
        for (int i = tid; i < NE * NL; i += 256) phis[i] = phi[i];
    }

    float acc2[8][4];
#pragma unroll
    for (int n = 0; n < 8; n++)
#pragma unroll
        for (int r = 0; r < 4; r++) acc2[n][r] = 0.0f;

    // prologue: W2 + stages 0,1 of nc=0
    issue_w2(sb, 0, tid);
    issue_g1(sb + SM_STG0, 0, 0, rowBase, tid);
    issue_g1(sb + SM_STG1, 0, 1, rowBase, tid);

#pragma unroll 1
    for (int nc = 0; nc < 3; nc++) {
        float acc1[2][8][4];
#pragma unroll
        for (int m = 0; m < 2; m++)
#pragma unroll
            for (int n = 0; n < 8; n++)
#pragma unroll
                for (int r = 0; r < 4; r++) acc1[m][n][r] = 0.0f;

#pragma unroll 1
        for (int k8 = 0; k8 < 8; k8++) {
            if (k8 == 7) { CP_WAIT0(); } else { CP_WAIT1(); }
            __syncthreads();

            const uint32_t sbuf = sb + ((k8 & 1) ? SM_STG1 : SM_STG0);
            // ---- GEMM1 mma on this k32 stage: 3 passes ----
#pragma unroll
            for (int pass = 0; pass < 3; pass++) {
                uint32_t Ab = sbuf + (pass == 2 ? XLO_OFF : 0)
                            + (wm + a_dr) * 80 + a_dc * 2;
                uint32_t Bb = sbuf + W1_OFF + (pass == 1 ? W1LO : 0)
                            + a_dr * 272 + (wn + a_dc) * 2;
#pragma unroll
                for (int k16 = 0; k16 < 2; k16++) {
                    uint32_t a0[4], a1[4];
                    LDM_X4(a0, Ab + k16 * 32);
                    LDM_X4(a1, Ab + k16 * 32 + 16 * 80);
#pragma unroll
                    for (int p = 0; p < 4; p++) {
                        uint32_t bq[4];
                        LDM_X4_T(bq, Bb + k16 * 4352 + p * 32);
                        mma_bf16(acc1[0][2 * p],     a0, bq);
                        mma_bf16(acc1[0][2 * p + 1], a0, bq + 2);
                        mma_bf16(acc1[1][2 * p],     a1, bq);
                        mma_bf16(acc1[1][2 * p + 1], a1, bq + 2);
                    }
                }
            }
            __syncthreads();   // buffer reads done
            if (k8 < 6) issue_g1(sbuf, nc, k8 + 2, rowBase, tid);
        }

        // ---- epilogue1: h = sigmoid(acc1 + b1) -> Hs hi/lo (over stages) ----
#pragma unroll
        for (int m = 0; m < 2; m++) {
            int row0 = wm + m * 16 + g;
#pragma unroll
            for (int n = 0; n < 8; n++) {
                int col = wn + n * 8 + 2 * tg;
                float2 bb = __ldg((const float2*)(b1 + nc * 128 + col));
                float f0 = fsigmoid(acc1[m][n][0] + bb.x);
                float f1 = fsigmoid(acc1[m][n][1] + bb.y);
                float f2 = fsigmoid(acc1[m][n][2] + bb.x);
                float f3 = fsigmoid(acc1[m][n][3] + bb.y);
                __nv_bfloat162 h01 = __float22bfloat162_rn(make_float2(f0, f1));
                __nv_bfloat162 h23 = __float22bfloat162_rn(make_float2(f2, f3));
                __nv_bfloat162 l01 = __float22bfloat162_rn(make_float2(
                    f0 - __bfloat162float(h01.x), f1 - __bfloat162float(h01.y)));
                __nv_bfloat162 l23 = __float22bfloat162_rn(make_float2(
                    f2 - __bfloat162float(h23.x), f3 - __bfloat162float(h23.y)));
                *(uint32_t*)(smem + row0 * 272 + col * 2)                 = *(uint32_t*)&h01;
                *(uint32_t*)(smem + (row0 + 8) * 272 + col * 2)           = *(uint32_t*)&h23;
                *(uint32_t*)(smem + 34816 + row0 * 272 + col * 2)         = *(uint32_t*)&l01;
                *(uint32_t*)(smem + 34816 + (row0 + 8) * 272 + col * 2)   = *(uint32_t*)&l23;
            }
        }
        __syncthreads();       // Hs visible; W2 already arrived (waited @k8=0)

        // ---- GEMM2 mma: acc2 += Hc @ W2c, 3 passes ----
#pragma unroll 1
        for (int pass = 0; pass < 3; pass++) {
            uint32_t Ab = sb + (pass == 2 ? 34816 : 0)
                        + (wm2 + a_dr) * 272 + a_dc * 2;
            uint32_t Bb = sb + SM_W2 + (pass == 1 ? 17408 : 0)
                        + b_dn * 272 + b_dk * 2;
#pragma unroll
            for (int k16 = 0; k16 < 8; k16++) {
                uint32_t a0[4];
                LDM_X4(a0, Ab + k16 * 32);
#pragma unroll
                for (int p = 0; p < 4; p++) {
                    uint32_t bq[4];
                    LDM_X4(bq, Bb + k16 * 32 + p * 16 * 272);
                    mma_bf16(acc2[2 * p],     a0, bq);
                    mma_bf16(acc2[2 * p + 1], a0, bq + 2);
                }
            }
        }
        __syncthreads();       // Hs/W2 reads done

        if (nc < 2) {          // prefetch next nc
            issue_w2(sb, nc + 1, tid);
            issue_g1(sb + SM_STG0, nc + 1, 0, rowBase, tid);
            issue_g1(sb + SM_STG1, nc + 1, 1, rowBase, tid);
        }
    }

    // ---- latent = sigmoid(acc2 + b2) -> lat (overlays stage region) ----
    float* lat = (float*)smem;
#pragma unroll
    for (int n = 0; n < 8; n++) {
        int c0 = n * 8 + 2 * tg;
        float2 bb = __ldg((const float2*)(b2 + c0));
        lat[(wm2 + g) * 65 + c0]         = fsigmoid(acc2[n][0] + bb.x);
        lat[(wm2 + g) * 65 + c0 + 1]     = fsigmoid(acc2[n][1] + bb.y);
        lat[(wm2 + g + 8) * 65 + c0]     = fsigmoid(acc2[n][2] + bb.x);
        lat[(wm2 + g + 8) * 65 + c0 + 1] = fsigmoid(acc2[n][3] + bb.y);
    }
    __syncthreads();

    // ---- tree + pi contraction (pi via L1-cached global) ----
    {
        const int row = tid & 127;
        const int obase = (tid >> 7) * 8;   // 0 or 8
        const float* latrow = lat + row * 65;
        const int* phis = (const int*)(smem + SM_PHI);
        float accO[8];
#pragma unroll
        for (int o = 0; o < 8; o++) accO[o] = 0.0f;

#pragma unroll 1
        for (int e = 0; e < NE; e++) {
            const int* phie = phis + e * NL;
            float mu[64];
            mu[0] = 1.0f;
#pragma unroll
            for (int lev = 0; lev < 6; lev++) {
#pragma unroll
                for (int j = (1 << lev) - 1; j >= 0; j--) {
                    int node = (1 << lev) + j;
                    float d = latrow[phie[node]];
                    float p = mu[j];
                    mu[2 * j + 1] = p * (1.0f - d);
                    mu[2 * j]     = p * d;
                }
            }
            const float* pie = pi + e * NL * NO + obase;
#pragma unroll
            for (int l = 0; l < NL; l++) {
                float m = mu[l];
                float4 p0 = __ldg((const float4*)(pie + l * NO));
                float4 p1 = __ldg((const float4*)(pie + l * NO + 4));
                accO[0] = fmaf(m, p0.x, accO[0]);
                accO[1] = fmaf(m, p0.y, accO[1]);
                accO[2] = fmaf(m, p0.z, accO[2]);
                accO[3] = fmaf(m, p0.w, accO[3]);
                accO[4] = fmaf(m, p1.x, accO[4]);
                accO[5] = fmaf(m, p1.y, accO[5]);
                accO[6] = fmaf(m, p1.z, accO[6]);
                accO[7] = fmaf(m, p1.w, accO[7]);
            }
        }
        float4 o0, o1;
        o0.x = accO[0] * 0.2f; o0.y = accO[1] * 0.2f;
        o0.z = accO[2] * 0.2f; o0.w = accO[3] * 0.2f;
        o1.x = accO[4] * 0.2f; o1.y = accO[5] * 0.2f;
        o1.z = accO[6] * 0.2f; o1.w = accO[7] * 0.2f;
        float* op = out + (rowBase + row) * NO + obase;
        *(float4*)op       = o0;
        *(float4*)(op + 4) = o1;
    }
}

// ---------------------------------------------------------------------------
extern "C" void kernel_launch(void* const* d_in, const int* in_sizes, int n_in,
                              void* d_out, int out_size) {
    const float* X   = (const float*)d_in[0];
    const float* W1  = (const float*)d_in[1];
    const float* b1  = (const float*)d_in[2];
    const float* W2  = (const float*)d_in[3];
    const float* b2  = (const float*)d_in[4];
    const int*   phi = (const int*)d_in[5];
    const float* pi  = (const float*)d_in[6];
    float* out = (float*)d_out;

    const int N = in_sizes[0] / NF;   // 131072

    cudaFuncSetAttribute(fused_all, cudaFuncAttributeMaxDynamicSharedMemorySize,
                         SMEM_TOTAL);

    prep_x<<<(size_t)N * NF / 4 / 256, 256>>>(X);
    prep_w<<<384, 256>>>(W1, W2);
    fused_all<<<N / 128, 256, SMEM_TOTAL>>>(b1, b2, phi, pi, out);
}

// round 15
// speedup vs baseline: 1.3679x; 1.3679x over previous
#include <cuda_runtime.h>
#include <cuda_fp16.h>
#include <cstdint>

// Shapes: X[131072,256], W1[256,384], b1[384], W2[384,64], b2[64],
//         phi[5,64] i32, pi[5,64,16], out[131072,16]
#define NF  256
#define NH  384
#define NL  64
#define NO  16
#define NE  5

// ---------------------------------------------------------------------------
// Pre-split global tables (fp16), written by prep kernels each launch.
//   gX  : X rounded to fp16, plain layout (single array — A stays unsplit)
//   gW1 : [s][nc(3)][k4(4)][n=128][k=64]  fp16 hi/lo  (B operand, 2-pass)
//   gW2 : [s][nc(3)][n=64][k=128]         fp16 hi/lo
// ---------------------------------------------------------------------------
__device__ __align__(16) __half gX[131072UL * 256UL];
__device__ __align__(16) __half gW1[2][98304];
__device__ __align__(16) __half gW2[2][24576];

__global__ void prep_x(const float* __restrict__ X) {
    size_t idx = (size_t)blockIdx.x * 256 + threadIdx.x;
    float4 v = *(const float4*)(X + idx * 4);
    __half2 h01 = __floats2half2_rn(v.x, v.y);
    __half2 h23 = __floats2half2_rn(v.z, v.w);
    uint2 hp;
    hp.x = *(uint32_t*)&h01; hp.y = *(uint32_t*)&h23;
    *(uint2*)(gX + idx * 4) = hp;
}

__global__ void prep_w(const float* __restrict__ W1, const float* __restrict__ W2) {
    int idx = blockIdx.x * 256 + threadIdx.x;
    if (idx < 98304) {
        // dst: [nc][k4][n 128][k 64]
        int k  = idx & 63;
        int n  = (idx >> 6) & 127;
        int k4 = (idx >> 13) & 3;
        int nc = idx >> 15;
        float v = W1[(size_t)(k4 * 64 + k) * NH + nc * 128 + n];
        __half hi = __float2half_rn(v);
        __half lo = __float2half_rn(v - __half2float(hi));
        gW1[0][idx] = hi;
        gW1[1][idx] = lo;
    }
    if (idx < 24576) {
        // dst: [nc][n 64][k 128]
        int k  = idx & 127;
        int n  = (idx >> 7) & 63;
        int nc = idx >> 13;
        float v = W2[(size_t)(nc * 128 + k) * NL + n];
        __half hi = __float2half_rn(v);
        __half lo = __float2half_rn(v - __half2float(hi));
        gW2[0][idx] = hi;
        gW2[1][idx] = lo;
    }
}

// ---------------------------------------------------------------------------
// PTX helpers
// ---------------------------------------------------------------------------
__device__ __forceinline__ uint32_t smem_u32(const void* p) {
    uint32_t a;
    asm("{ .reg .u64 t; cvta.to.shared.u64 t, %1; cvt.u32.u64 %0, t; }"
        : "=r"(a) : "l"(p));
    return a;
}

#define CP16(dst, src) \
    asm volatile("cp.async.cg.shared.global [%0], [%1], 16;" :: "r"(dst), "l"(src))
#define CP_COMMIT() asm volatile("cp.async.commit_group;" ::: "memory")
#define CP_WAIT0()  asm volatile("cp.async.wait_group 0;" ::: "memory")

#define LDM_X4(r, addr) \
    asm volatile("ldmatrix.sync.aligned.m8n8.x4.shared.b16 {%0,%1,%2,%3}, [%4];" \
        : "=r"((r)[0]), "=r"((r)[1]), "=r"((r)[2]), "=r"((r)[3]) : "r"(addr))

__device__ __forceinline__ void mma_f16(float* c, const uint32_t* a, const uint32_t* b) {
    asm volatile("mma.sync.aligned.m16n8k16.row.col.f32.f16.f16.f32 "
        "{%0,%1,%2,%3}, {%4,%5,%6,%7}, {%8,%9}, {%0,%1,%2,%3};"
        : "+f"(c[0]), "+f"(c[1]), "+f"(c[2]), "+f"(c[3])
        : "r"(a[0]), "r"(a[1]), "r"(a[2]), "r"(a[3]), "r"(b[0]), "r"(b[1]));
}

__device__ __forceinline__ float fsigmoid(float v) {
    return 1.0f / (1.0f + __expf(-v));
}

// ---------------------------------------------------------------------------
// SMEM layout (bytes), 93184 total -> 2 CTAs/SM:
//   stage (55296): [X 18432][W1H 18432][W1L 18432]
//     X tile [128 m][64 k] fp16, 144 B rows; W1 tiles [128 n][64 k], 144 B rows
//   after GEMM1: Hs [128 m][128 k] fp16 @0 (34816, 272 B rows)
//   after GEMM2: lat [128][65] f32 @0 (33280)
//   SM_W2  = 55296 : W2 hi 17408 @55296, lo @72704  ([64 n][128 k], 272 B rows)
//   SM_PHI = 90112 (1280) | SM_B1 = 91392 (1536) | SM_B2 = 92928 (256)
// ---------------------------------------------------------------------------
#define W1H_OFF 18432
#define W1L_OFF 36864
#define SM_W2   55296
#define W2LO    17408
#define SM_PHI  90112
#define SM_B1   91392
#define SM_B2   92928
#define SMEM_TOTAL 93184

__device__ __forceinline__ void issue_g1(uint32_t sbuf, int nc, int k4,
                                         size_t rowBase, int tid) {
    // X tile: 128 rows x 8 16B-chunks
#pragma unroll
    for (int i = 0; i < 4; i++) {
        int j = tid + i * 256;
        int row = j >> 3, c = j & 7;
        CP16(sbuf + row * 144 + c * 16,
             gX + (rowBase + row) * NF + k4 * 64 + c * 8);
    }
    // W1 tiles hi/lo: 128 n-rows x 8 chunks each
    const int wbase = (nc * 4 + k4) * 128 * 64;
#pragma unroll
    for (int i = 0; i < 4; i++) {
        int j = tid + i * 256;
        int n = j >> 3, c = j & 7;
        uint32_t d = sbuf + W1H_OFF + n * 144 + c * 16;
        CP16(d,                     gW1[0] + wbase + n * 64 + c * 8);
        CP16(d + (W1L_OFF - W1H_OFF), gW1[1] + wbase + n * 64 + c * 8);
    }
    CP_COMMIT();
}

__device__ __forceinline__ void issue_w2(uint32_t sb, int nc, int tid) {
#pragma unroll
    for (int i = 0; i < 4; i++) {
        int j = tid + i * 256;
        int n = j >> 4, c = j & 15;
        uint32_t d = sb + SM_W2 + n * 272 + c * 16;
        CP16(d,        gW2[0] + (nc * 64 + n) * 128 + c * 8);
        CP16(d + W2LO, gW2[1] + (nc * 64 + n) * 128 + c * 8);
    }
    CP_COMMIT();
}

__global__ __launch_bounds__(256, 2)
void fused_all(const float* __restrict__ b1, const float* __restrict__ b2,
               const int* __restrict__ phi, const float* __restrict__ pi,
               float* __restrict__ out) {
    extern __shared__ char smem[];
    const uint32_t sb = smem_u32(smem);
    const int tid = threadIdx.x;
    const int wid = tid >> 5;
    const int lane = tid & 31;
    const int g = lane >> 2;
    const int tg = lane & 3;
    const size_t rowBase = (size_t)blockIdx.x * 128;

    const int a_dr = lane & 15;
    const int a_dc = (lane >> 4) * 8;
    const int b_dn = (lane & 7) + (lane >> 4) * 8;
    const int b_dk = ((lane >> 3) & 1) * 8;

    // GEMM1: 4x2 warp grid, 32 rows x 64 cols per warp
    const int wm = (wid & 3) * 32;
    const int wn = (wid >> 2) * 64;
    // GEMM2: 8x1 grid, 16 rows x 64 cols per warp
    const int wm2 = wid * 16;

    // ---- stage constants ----
    {
        int* phis = (int*)(smem + SM_PHI);
        for (int i = tid; i < NE * NL; i += 256) phis[i] = phi[i];
        float* b1s = (float*)(smem + SM_B1);
        for (int i = tid; i < NH; i += 256) b1s[i] = b1[i];
        float* b2s = (float*)(smem + SM_B2);
        if (tid < NL) b2s[tid] = b2[tid];
    }

    const float* b1s = (const float*)(smem + SM_B1);
    const float* b2s = (const float*)(smem + SM_B2);

    float acc2[8][4];
#pragma unroll
    for (int n = 0; n < 8; n++)
#pragma unroll
        for (int r = 0; r < 4; r++) acc2[n][r] = 0.0f;

#pragma unroll 1
    for (int nc = 0; nc < 3; nc++) {
        float acc1[2][8][4];
#pragma unroll
        for (int m = 0; m < 2; m++)
#pragma unroll
            for (int n = 0; n < 8; n++)
#pragma unroll
                for (int r = 0; r < 4; r++) acc1[m][n][r] = 0.0f;

        issue_w2(sb, nc, tid);     // dedicated region, arrives with stage 0

#pragma unroll 1
        for (int k4 = 0; k4 < 4; k4++) {
            issue_g1(sb, nc, k4, rowBase, tid);
            CP_WAIT0();
            __syncthreads();

            // ---- GEMM1 mma: A single fp16, B = W1hi + W1lo (same acc) ----
            uint32_t Ab = sb + (wm + a_dr) * 144 + a_dc * 2;
            uint32_t Bh = sb + W1H_OFF + (wn + b_dn) * 144 + b_dk * 2;
#pragma unroll
            for (int k16 = 0; k16 < 4; k16++) {
                uint32_t a0[4], a1[4];
                LDM_X4(a0, Ab + k16 * 32);
                LDM_X4(a1, Ab + k16 * 32 + 16 * 144);
#pragma unroll
                for (int p = 0; p < 4; p++) {
                    uint32_t bq[4];
                    LDM_X4(bq, Bh + k16 * 32 + p * 16 * 144);
                    mma_f16(acc1[0][2 * p],     a0, bq);
                    mma_f16(acc1[0][2 * p + 1], a0, bq + 2);
                    mma_f16(acc1[1][2 * p],     a1, bq);
                    mma_f16(acc1[1][2 * p + 1], a1, bq + 2);
                    uint32_t bl[4];
                    LDM_X4(bl, Bh + (W1L_OFF - W1H_OFF) + k16 * 32 + p * 16 * 144);
                    mma_f16(acc1[0][2 * p],     a0, bl);
                    mma_f16(acc1[0][2 * p + 1], a0, bl + 2);
                    mma_f16(acc1[1][2 * p],     a1, bl);
                    mma_f16(acc1[1][2 * p + 1], a1, bl + 2);
                }
            }
            __syncthreads();   // buffer reads done before next stage overwrites
        }

        // ---- epilogue1: h = sigmoid(acc1 + b1) -> Hs single fp16 @0 ----
#pragma unroll
        for (int m = 0; m < 2; m++) {
            int row0 = wm + m * 16 + g;
#pragma unroll
            for (int n = 0; n < 8; n++) {
                int col = wn + n * 8 + 2 * tg;
                float bb0 = b1s[nc * 128 + col];
                float bb1 = b1s[nc * 128 + col + 1];
                __half2 h01 = __floats2half2_rn(fsigmoid(acc1[m][n][0] + bb0),
                                                fsigmoid(acc1[m][n][1] + bb1));
                __half2 h23 = __floats2half2_rn(fsigmoid(acc1[m][n][2] + bb0),
                                                fsigmoid(acc1[m][n][3] + bb1));
                *(uint32_t*)(smem + row0 * 272 + col * 2)       = *(uint32_t*)&h01;
                *(uint32_t*)(smem + (row0 + 8) * 272 + col * 2) = *(uint32_t*)&h23;
            }
        }
        __syncthreads();       // Hs visible; W2 already arrived (waited @k4=0)

        // ---- GEMM2 mma: acc2 += Hs @ (W2hi + W2lo) ----
        {
            uint32_t Ab = sb + (wm2 + a_dr) * 272 + a_dc * 2;
            uint32_t Bh = sb + SM_W2 + b_dn * 272 + b_dk * 2;
#pragma unroll
            for (int k16 = 0; k16 < 8; k16++) {
                uint32_t a0[4];
                LDM_X4(a0, Ab + k16 * 32);
#pragma unroll
                for (int p = 0; p < 4; p++) {
                    uint32_t bq[4];
                    LDM_X4(bq, Bh + k16 * 32 + p * 16 * 272);
                    mma_f16(acc2[2 * p],     a0, bq);
                    mma_f16(acc2[2 * p + 1], a0, bq + 2);
                    uint32_t bl[4];
                    LDM_X4(bl, Bh + W2LO + k16 * 32 + p * 16 * 272);
                    mma_f16(acc2[2 * p],     a0, bl);
                    mma_f16(acc2[2 * p + 1], a0, bl + 2);
                }
            }
        }
        __syncthreads();       // Hs/W2 reads done before next nc overwrites
    }

    // ---- latent = sigmoid(acc2 + b2) -> lat (overlays stage region) ----
    float* lat = (float*)smem;
#pragma unroll
    for (int n = 0; n < 8; n++) {
        int c0 = n * 8 + 2 * tg;
        lat[(wm2 + g) * 65 + c0]         = fsigmoid(acc2[n][0] + b2s[c0]);
        lat[(wm2 + g) * 65 + c0 + 1]     = fsigmoid(acc2[n][1] + b2s[c0 + 1]);
        lat[(wm2 + g + 8) * 65 + c0]     = fsigmoid(acc2[n][2] + b2s[c0]);
        lat[(wm2 + g + 8) * 65 + c0 + 1] = fsigmoid(acc2[n][3] + b2s[c0 + 1]);
    }
    __syncthreads();

    // ---- tree + pi contraction (pi via L1-cached global) ----
    {
        const int row = tid & 127;
        const int obase = (tid >> 7) * 8;   // 0 or 8
        const float* latrow = lat + row * 65;
        const int* phis = (const int*)(smem + SM_PHI);
        float accO[8];
#pragma unroll
        for (int o = 0; o < 8; o++) accO[o] = 0.0f;

#pragma unroll 1
        for (int e = 0; e < NE; e++) {
            const int* phie = phis + e * NL;
            float mu[64];
            mu[0] = 1.0f;
#pragma unroll
            for (int lev = 0; lev < 6; lev++) {
#pragma unroll
                for (int j = (1 << lev) - 1; j >= 0; j--) {
                    int node = (1 << lev) + j;
                    float d = latrow[phie[node]];
                    float p = mu[j];
                    mu[2 * j + 1] = p * (1.0f - d);
                    mu[2 * j]     = p * d;
                }
            }
            const float* pie = pi + e * NL * NO + obase;
#pragma unroll
            for (int l = 0; l < NL; l++) {
                float m = mu[l];
                float4 p0 = __ldg((const float4*)(pie + l * NO));
                float4 p1 = __ldg((const float4*)(pie + l * NO + 4));
                accO[0] = fmaf(m, p0.x, accO[0]);
                accO[1] = fmaf(m, p0.y, accO[1]);
                accO[2] = fmaf(m, p0.z, accO[2]);
                accO[3] = fmaf(m, p0.w, accO[3]);
                accO[4] = fmaf(m, p1.x, accO[4]);
                accO[5] = fmaf(m, p1.y, accO[5]);
                accO[6] = fmaf(m, p1.z, accO[6]);
                accO[7] = fmaf(m, p1.w, accO[7]);
            }
        }
        float4 o0, o1;
        o0.x = accO[0] * 0.2f; o0.y = accO[1] * 0.2f;
        o0.z = accO[2] * 0.2f; o0.w = accO[3] * 0.2f;
        o1.x = accO[4] * 0.2f; o1.y = accO[5] * 0.2f;
        o1.z = accO[6] * 0.2f; o1.w = accO[7] * 0.2f;
        float* op = out + (rowBase + row) * NO + obase;
        *(float4*)op       = o0;
        *(float4*)(op + 4) = o1;
    }
}

// ---------------------------------------------------------------------------
extern "C" void kernel_launch(void* const* d_in, const int* in_sizes, int n_in,
                              void* d_out, int out_size) {
    const float* X   = (const float*)d_in[0];
    const float* W1  = (const float*)d_in[1];
    const float* b1  = (const float*)d_in[2];
    const float* W2  = (const float*)d_in[3];
    const float* b2  = (const float*)d_in[4];
    const int*   phi = (const int*)d_in[5];
    const float* pi  = (const float*)d_in[6];
    float* out = (float*)d_out;

    const int N = in_sizes[0] / NF;   // 131072

    cudaFuncSetAttribute(fused_all, cudaFuncAttributeMaxDynamicSharedMemorySize,
                         SMEM_TOTAL);

    prep_x<<<(size_t)N * NF / 4 / 256, 256>>>(X);
    prep_w<<<384, 256>>>(W1, W2);
    fused_all<<<N / 128, 256, SMEM_TOTAL>>>(b1, b2, phi, pi, out);
}

// round 17
// speedup vs baseline: 1.5719x; 1.1491x over previous
#include <cuda_runtime.h>
#include <cuda_fp16.h>
#include <cstdint>

// Shapes: X[131072,256], W1[256,384], b1[384], W2[384,64], b2[64],
//         phi[5,64] i32, pi[5,64,16], out[131072,16]
#define NF  256
#define NH  384
#define NL  64
#define NO  16
#define NE  5

// ---------------------------------------------------------------------------
// Pre-converted global tables (fp16, single precision pass), per launch.
//   gX  : X rounded to fp16, plain layout
//   gW1 : [nc(3)][k4(4)][n=128][k=64]  fp16
//   gW2 : [nc(3)][n=64][k=128]         fp16
// ---------------------------------------------------------------------------
__device__ __align__(16) __half gX[131072UL * 256UL];
__device__ __align__(16) __half gW1[98304];
__device__ __align__(16) __half gW2[24576];

__global__ void prep_x(const float* __restrict__ X) {
    size_t idx = (size_t)blockIdx.x * 256 + threadIdx.x;
    float4 v = *(const float4*)(X + idx * 4);
    __half2 h01 = __floats2half2_rn(v.x, v.y);
    __half2 h23 = __floats2half2_rn(v.z, v.w);
    uint2 hp;
    hp.x = *(uint32_t*)&h01; hp.y = *(uint32_t*)&h23;
    *(uint2*)(gX + idx * 4) = hp;
}

__global__ void prep_w(const float* __restrict__ W1, const float* __restrict__ W2) {
    int idx = blockIdx.x * 256 + threadIdx.x;
    if (idx < 98304) {
        // dst: [nc][k4][n 128][k 64]
        int k  = idx & 63;
        int n  = (idx >> 6) & 127;
        int k4 = (idx >> 13) & 3;
        int nc = idx >> 15;
        gW1[idx] = __float2half_rn(W1[(size_t)(k4 * 64 + k) * NH + nc * 128 + n]);
    }
    if (idx < 24576) {
        // dst: [nc][n 64][k 128]
        int k  = idx & 127;
        int n  = (idx >> 7) & 63;
        int nc = idx >> 13;
        gW2[idx] = __float2half_rn(W2[(size_t)(nc * 128 + k) * NL + n]);
    }
}

// ---------------------------------------------------------------------------
// PTX helpers
// ---------------------------------------------------------------------------
__device__ __forceinline__ uint32_t smem_u32(const void* p) {
    uint32_t a;
    asm("{ .reg .u64 t; cvta.to.shared.u64 t, %1; cvt.u32.u64 %0, t; }"
        : "=r"(a) : "l"(p));
    return a;
}

#define CP16(dst, src) \
    asm volatile("cp.async.cg.shared.global [%0], [%1], 16;" :: "r"(dst), "l"(src))
#define CP_COMMIT() asm volatile("cp.async.commit_group;" ::: "memory")
#define CP_WAIT0()  asm volatile("cp.async.wait_group 0;" ::: "memory")

#define LDM_X4(r, addr) \
    asm volatile("ldmatrix.sync.aligned.m8n8.x4.shared.b16 {%0,%1,%2,%3}, [%4];" \
        : "=r"((r)[0]), "=r"((r)[1]), "=r"((r)[2]), "=r"((r)[3]) : "r"(addr))

__device__ __forceinline__ void mma_f16(float* c, const uint32_t* a, const uint32_t* b) {
    asm volatile("mma.sync.aligned.m16n8k16.row.col.f32.f16.f16.f32 "
        "{%0,%1,%2,%3}, {%4,%5,%6,%7}, {%8,%9}, {%0,%1,%2,%3};"
        : "+f"(c[0]), "+f"(c[1]), "+f"(c[2]), "+f"(c[3])
        : "r"(a[0]), "r"(a[1]), "r"(a[2]), "r"(a[3]), "r"(b[0]), "r"(b[1]));
}

__device__ __forceinline__ float fsigmoid(float v) {
    return 1.0f / (1.0f + __expf(-v));
}

// ---------------------------------------------------------------------------
// SMEM layout (bytes), 57344 total -> 2 CTAs/SM:
//   stage (36864): [X 18432][W1 18432]
//     X tile [128 m][64 k] fp16, 144 B rows; W1 tile [128 n][64 k], 144 B rows
//   after GEMM1: Hs [128 m][128 k] fp16 @0 (34816, 272 B rows)
//   after GEMM2: lat [128][65] f32 @0 (33280)
//   SM_W2  = 36864 : W2 17408 ([64 n][128 k], 272 B rows)
//   SM_PHI = 54272 (1280) | SM_B1 = 55552 (1536) | SM_B2 = 57088 (256)
// ---------------------------------------------------------------------------
#define W1_OFF  18432
#define SM_W2   36864
#define SM_PHI  54272
#define SM_B1   55552
#define SM_B2   57088
#define SMEM_TOTAL 57344

__device__ __forceinline__ void issue_g1(uint32_t sbuf, int nc, int k4,
                                         size_t rowBase, int tid) {
    // X tile: 128 rows x 8 16B-chunks
#pragma unroll
    for (int i = 0; i < 4; i++) {
        int j = tid + i * 256;
        int row = j >> 3, c = j & 7;
        CP16(sbuf + row * 144 + c * 16,
             gX + (rowBase + row) * NF + k4 * 64 + c * 8);
    }
    // W1 tile: 128 n-rows x 8 chunks
    const int wbase = (nc * 4 + k4) * 128 * 64;
#pragma unroll
    for (int i = 0; i < 4; i++) {
        int j = tid + i * 256;
        int n = j >> 3, c = j & 7;
        CP16(sbuf + W1_OFF + n * 144 + c * 16,
             gW1 + wbase + n * 64 + c * 8);
    }
    CP_COMMIT();
}

__device__ __forceinline__ void issue_w2(uint32_t sb, int nc, int tid) {
#pragma unroll
    for (int i = 0; i < 4; i++) {
        int j = tid + i * 256;
        int n = j >> 4, c = j & 15;
        CP16(sb + SM_W2 + n * 272 + c * 16,
             gW2 + (nc * 64 + n) * 128 + c * 8);
    }
    CP_COMMIT();
}

__global__ __launch_bounds__(256, 2)
void fused_all(const float* __restrict__ b1, const float* __restrict__ b2,
               const int* __restrict__ phi, const float* __restrict__ pi,
               float* __restrict__ out) {
    extern __shared__ char smem[];
    const uint32_t sb = smem_u32(smem);
    const int tid = threadIdx.x;
    const int wid = tid >> 5;
    const int lane = tid & 31;
    const int g = lane >> 2;
    const int tg = lane & 3;
    const size_t rowBase = (size_t)blockIdx.x * 128;

    const int a_dr = lane & 15;
    const int a_dc = (lane >> 4) * 8;
    const int b_dn = (lane & 7) + (lane >> 4) * 8;
    const int b_dk = ((lane >> 3) & 1) * 8;

    // GEMM1: 4x2 warp grid, 32 rows x 64 cols per warp
    const int wm = (wid & 3) * 32;
    const int wn = (wid >> 2) * 64;
    // GEMM2: 8x1 grid, 16 rows x 64 cols per warp
    const int wm2 = wid * 16;

    // ---- stage constants ----
    {
        int* phis = (int*)(smem + SM_PHI);
        for (int i = tid; i < NE * NL; i += 256) phis[i] = phi[i];
        float* b1s = (float*)(smem + SM_B1);
        for (int i = tid; i < NH; i += 256) b1s[i] = b1[i];
        float* b2s = (float*)(smem + SM_B2);
        if (tid < NL) b2s[tid] = b2[tid];
    }

    const float* b1s = (const float*)(smem + SM_B1);
    const float* b2s = (const float*)(smem + SM_B2);

    float acc2[8][4];
#pragma unroll
    for (int n = 0; n < 8; n++)
#pragma unroll
        for (int r = 0; r < 4; r++) acc2[n][r] = 0.0f;

#pragma unroll 1
    for (int nc = 0; nc < 3; nc++) {
        float acc1[2][8][4];
#pragma unroll
        for (int m = 0; m < 2; m++)
#pragma unroll
            for (int n = 0; n < 8; n++)
#pragma unroll
                for (int r = 0; r < 4; r++) acc1[m][n][r] = 0.0f;

        issue_w2(sb, nc, tid);     // dedicated region, arrives with stage 0

#pragma unroll 1
        for (int k4 = 0; k4 < 4; k4++) {
            issue_g1(sb, nc, k4, rowBase, tid);
            CP_WAIT0();
            __syncthreads();

            // ---- GEMM1 mma: single-pass fp16 ----
            uint32_t Ab = sb + (wm + a_dr) * 144 + a_dc * 2;
            uint32_t Bb = sb + W1_OFF + (wn + b_dn) * 144 + b_dk * 2;
#pragma unroll
            for (int k16 = 0; k16 < 4; k16++) {
                uint32_t a0[4], a1[4];
                LDM_X4(a0, Ab + k16 * 32);
                LDM_X4(a1, Ab + k16 * 32 + 16 * 144);
#pragma unroll
                for (int p = 0; p < 4; p++) {
                    uint32_t bq[4];
                    LDM_X4(bq, Bb + k16 * 32 + p * 16 * 144);
                    mma_f16(acc1[0][2 * p],     a0, bq);
                    mma_f16(acc1[0][2 * p + 1], a0, bq + 2);
                    mma_f16(acc1[1][2 * p],     a1, bq);
                    mma_f16(acc1[1][2 * p + 1], a1, bq + 2);
                }
            }
            __syncthreads();   // buffer reads done before next stage overwrites
        }

        // ---- epilogue1: h = sigmoid(acc1 + b1) -> Hs fp16 @0 ----
#pragma unroll
        for (int m = 0; m < 2; m++) {
            int row0 = wm + m * 16 + g;
#pragma unroll
            for (int n = 0; n < 8; n++) {
                int col = wn + n * 8 + 2 * tg;
                float bb0 = b1s[nc * 128 + col];
                float bb1 = b1s[nc * 128 + col + 1];
                __half2 h01 = __floats2half2_rn(fsigmoid(acc1[m][n][0] + bb0),
                                                fsigmoid(acc1[m][n][1] + bb1));
                __half2 h23 = __floats2half2_rn(fsigmoid(acc1[m][n][2] + bb0),
                                                fsigmoid(acc1[m][n][3] + bb1));
                *(uint32_t*)(smem + row0 * 272 + col * 2)       = *(uint32_t*)&h01;
                *(uint32_t*)(smem + (row0 + 8) * 272 + col * 2) = *(uint32_t*)&h23;
            }
        }
        __syncthreads();       // Hs visible; W2 already arrived (waited @k4=0)

        // ---- GEMM2 mma: acc2 += Hs @ W2 (single-pass) ----
        {
            uint32_t Ab = sb + (wm2 + a_dr) * 272 + a_dc * 2;
            uint32_t Bb = sb + SM_W2 + b_dn * 272 + b_dk * 2;
#pragma unroll
            for (int k16 = 0; k16 < 8; k16++) {
                uint32_t a0[4];
                LDM_X4(a0, Ab + k16 * 32);
#pragma unroll
                for (int p = 0; p < 4; p++) {
                    uint32_t bq[4];
                    LDM_X4(bq, Bb + k16 * 32 + p * 16 * 272);
                    mma_f16(acc2[2 * p],     a0, bq);
                    mma_f16(acc2[2 * p + 1], a0, bq + 2);
                }
            }
        }
        __syncthreads();       // Hs/W2 reads done before next nc overwrites
    }

    // ---- latent = sigmoid(acc2 + b2) -> lat (overlays stage region) ----
    float* lat = (float*)smem;
#pragma unroll
    for (int n = 0; n < 8; n++) {
        int c0 = n * 8 + 2 * tg;
        lat[(wm2 + g) * 65 + c0]         = fsigmoid(acc2[n][0] + b2s[c0]);
        lat[(wm2 + g) * 65 + c0 + 1]     = fsigmoid(acc2[n][1] + b2s[c0 + 1]);
        lat[(wm2 + g + 8) * 65 + c0]     = fsigmoid(acc2[n][2] + b2s[c0]);
        lat[(wm2 + g + 8) * 65 + c0 + 1] = fsigmoid(acc2[n][3] + b2s[c0 + 1]);
    }
    __syncthreads();

    // ---- tree + pi contraction (pi via L1-cached global) ----
    {
        const int row = tid & 127;
        const int obase = (tid >> 7) * 8;   // 0 or 8
        const float* latrow = lat + row * 65;
        const int* phis = (const int*)(smem + SM_PHI);
        float accO[8];
#pragma unroll
        for (int o = 0; o < 8; o++) accO[o] = 0.0f;

#pragma unroll 1
        for (int e = 0; e < NE; e++) {
            const int* phie = phis + e * NL;
            float mu[64];
            mu[0] = 1.0f;
#pragma unroll
            for (int lev = 0; lev < 6; lev++) {
#pragma unroll
                for (int j = (1 << lev) - 1; j >= 0; j--) {
                    int node = (1 << lev) + j;
                    float d = latrow[phie[node]];
                    float p = mu[j];
                    mu[2 * j + 1] = p * (1.0f - d);
                    mu[2 * j]     = p * d;
                }
            }
            const float* pie = pi + e * NL * NO + obase;
#pragma unroll
            for (int l = 0; l < NL; l++) {
                float m = mu[l];
                float4 p0 = __ldg((const float4*)(pie + l * NO));
                float4 p1 = __ldg((const float4*)(pie + l * NO + 4));
                accO[0] = fmaf(m, p0.x, accO[0]);
                accO[1] = fmaf(m, p0.y, accO[1]);
                accO[2] = fmaf(m, p0.z, accO[2]);
                accO[3] = fmaf(m, p0.w, accO[3]);
                accO[4] = fmaf(m, p1.x, accO[4]);
                accO[5] = fmaf(m, p1.y, accO[5]);
                accO[6] = fmaf(m, p1.z, accO[6]);
                accO[7] = fmaf(m, p1.w, accO[7]);
            }
        }
        float4 o0, o1;
        o0.x = accO[0] * 0.2f; o0.y = accO[1] * 0.2f;
        o0.z = accO[2] * 0.2f; o0.w = accO[3] * 0.2f;
        o1.x = accO[4] * 0.2f; o1.y = accO[5] * 0.2f;
        o1.z = accO[6] * 0.2f; o1.w = accO[7] * 0.2f;
        float* op = out + (rowBase + row) * NO + obase;
        *(float4*)op       = o0;
        *(float4*)(op + 4) = o1;
    }
}

// ---------------------------------------------------------------------------
extern "C" void kernel_launch(void* const* d_in, const int* in_sizes, int n_in,
                              void* d_out, int out_size) {
    const float* X   = (const float*)d_in[0];
    const float* W1  = (const float*)d_in[1];
    const float* b1  = (const float*)d_in[2];
    const float* W2  = (const float*)d_in[3];
    const float* b2  = (const float*)d_in[4];
    const int*   phi = (const int*)d_in[5];
    const float* pi  = (const float*)d_in[6];
    float* out = (float*)d_out;

    const int N = in_sizes[0] / NF;   // 131072

    cudaFuncSetAttribute(fused_all, cudaFuncAttributeMaxDynamicSharedMemorySize,
                         SMEM_TOTAL);

    prep_x<<<(size_t)N * NF / 4 / 256, 256>>>(X);
    prep_w<<<384, 256>>>(W1, W2);
    fused_all<<<N / 128, 256, SMEM_TOTAL>>>(b1, b2, phi, pi, out);
}